// round 13
// baseline (speedup 1.0000x reference)
#include <cuda_runtime.h>
#include <cuda_fp16.h>
#include <cstdint>
#include <math.h>

#define BATCH 8
#define SEQ   1024
#define DM    256
#define DI    512
#define NH    8
#define HD    64
#define NS    64
#define CDIM  640
#define DIP   1160
#define NTOK  (BATCH*SEQ)   // 8192
#define NPAD_IN 1280        // 10*128
#define NCH   8
#define CHUNK 128           // SEQ / NCH

// ---------------- device scratch ----------------
__device__ __align__(16) float g_x[NTOK*DM];
__device__ __align__(16) float g_zx[NTOK*DIP];
__device__ __align__(16) float g_xbc[NTOK*CDIM];
__device__ float g_dt[NTOK*NH];
__device__ float g_dA[NTOK*NH];
__device__ float g_pi[NTOK*NH];
__device__ __align__(16) float g_S[BATCH*NH*NCH*HD*NS];
__device__ __align__(16) float g_ys[NTOK*DI];
__device__ __align__(16) float g_lut[8*DIP];
__device__ float g_psum[BATCH*16*DM];
__device__ float g_pmax[BATCH*16*DM];
__device__ float g_pooled[BATCH*DM];
// fp16 2-term GEMM operands: A2 = [Ah | Al], W2 = [Wf | Wf]
__device__ __align__(16) __half g_a2[NTOK*2*DI];
__device__ __align__(16) __half g_x2[NTOK*2*DM];
__device__ __align__(16) __half g_w2a[NPAD_IN*2*DM];
__device__ __align__(16) __half g_w2b[DM*2*DI];

__device__ __forceinline__ float siluf(float x) { return x / (1.f + expf(-x)); }
__device__ __forceinline__ float geluf(float x) { return 0.5f * x * (1.f + erff(x * 0.7071067811865476f)); }

template<int N> __device__ __forceinline__ void cp_wait() {
    asm volatile("cp.async.wait_group %0;\n" :: "n"(N));
}
__device__ __forceinline__ void cp_commit() {
    asm volatile("cp.async.commit_group;\n");
}

// ---------------- layer-0 in_proj LUT ----------------
__global__ void k_lut(const float* __restrict__ emb, const float* __restrict__ W) {
    __shared__ float se[8*DM];
    for (int i = threadIdx.x; i < 8*DM; i += blockDim.x) se[i] = emb[i];
    __syncthreads();
    int e = blockIdx.x*blockDim.x + threadIdx.x;
    if (e >= DIP) return;
    float acc[8] = {0.f,0.f,0.f,0.f,0.f,0.f,0.f,0.f};
    const float* wr = W + (size_t)e*DM;
    for (int d = 0; d < DM; d++) {
        float wv = wr[d];
        #pragma unroll
        for (int v = 0; v < 8; v++) acc[v] += wv * se[v*DM + d];
    }
    #pragma unroll
    for (int v = 0; v < 8; v++) g_lut[(size_t)v*DIP + e] = acc[v];
}

// ---------------- conv4 + silu + softplus(dt) + dA ----------------
template<bool LUT0>
__global__ void k_conv(const float* __restrict__ cw, const float* __restrict__ cb,
                       const float* __restrict__ dtb, const float* __restrict__ Alog,
                       const int* __restrict__ ids) {
    int bt = blockIdx.x;
    int t  = bt & (SEQ-1);
    const float* rows[4];
    #pragma unroll
    for (int k = 0; k < 4; k++) {
        int tt = t - 3 + k;
        if (tt >= 0) {
            int src = bt - 3 + k;
            rows[k] = LUT0 ? (g_lut + (size_t)ids[src]*DIP) : (g_zx + (size_t)src*DIP);
        } else rows[k] = nullptr;
    }
    for (int c = threadIdx.x; c < CDIM; c += blockDim.x) {
        float acc = cb[c];
        #pragma unroll
        for (int k = 0; k < 4; k++)
            if (rows[k]) acc += rows[k][DI + c] * cw[c*4 + k];
        g_xbc[(size_t)bt*CDIM + c] = siluf(acc);
    }
    if (threadIdx.x < NH) {
        int h = threadIdx.x;
        float xr = (LUT0 ? g_lut[(size_t)ids[bt]*DIP + DI + CDIM + h]
                         : g_zx[(size_t)bt*DIP + DI + CDIM + h]) + dtb[h];
        float dtv = (xr > 20.f) ? xr : log1pf(expf(xr));
        g_dt[bt*NH + h] = dtv;
        g_dA[bt*NH + h] = expf(dtv * (-expf(Alog[h])));
    }
}

// ---------------- phase 1: local chunk scan (R11 staging + float4 B/C reads) ----------------
// 256 threads: p = tid>>2, q = tid&3; thread handles states n = q*16 + i.
__global__ void __launch_bounds__(256) k_scan1(const float* __restrict__ Dp) {
    int h = blockIdx.x, b = blockIdx.y, c = blockIdx.z;
    int tid = threadIdx.x;
    int p = tid >> 2, q = tid & 3;
    float Dh = Dp[h];
    float hreg[16];
    #pragma unroll
    for (int i = 0; i < 16; i++) hreg[i] = 0.f;
    float pi = 1.f;

    __shared__ float sx[16][64], sB[16][64], sC[16][64];
    __shared__ float sdt[16], sdA[16];

    int tbase = c*CHUNK;
    for (int tile = 0; tile < CHUNK/16; tile++) {
        int t0 = tbase + tile*16;
        for (int i = tid; i < 16*64; i += 256) {
            int s = i >> 6, j = i & 63;
            const float* row = g_xbc + (size_t)(b*SEQ + t0 + s)*CDIM;
            sx[s][j] = row[h*HD + j];
            sB[s][j] = row[DI + j];
            sC[s][j] = row[DI + NS + j];
        }
        if (tid < 16) {
            sdt[tid] = g_dt[(b*SEQ + t0 + tid)*NH + h];
            sdA[tid] = g_dA[(b*SEQ + t0 + tid)*NH + h];
        }
        __syncthreads();
        #pragma unroll 4
        for (int s = 0; s < 16; s++) {
            float da  = sdA[s];
            pi *= da;
            float xv  = sx[s][p];
            float dtx = sdt[s] * xv;
            float y = 0.f;
            #pragma unroll
            for (int u = 0; u < 4; u++) {
                float4 bv = *(const float4*)&sB[s][q*16 + u*4];
                float4 cv = *(const float4*)&sC[s][q*16 + u*4];
                hreg[u*4+0] = hreg[u*4+0]*da + dtx*bv.x;  y += hreg[u*4+0]*cv.x;
                hreg[u*4+1] = hreg[u*4+1]*da + dtx*bv.y;  y += hreg[u*4+1]*cv.y;
                hreg[u*4+2] = hreg[u*4+2]*da + dtx*bv.z;  y += hreg[u*4+2]*cv.z;
                hreg[u*4+3] = hreg[u*4+3]*da + dtx*bv.w;  y += hreg[u*4+3]*cv.w;
            }
            y += __shfl_xor_sync(0xffffffffu, y, 1);
            y += __shfl_xor_sync(0xffffffffu, y, 2);
            if (q == 0)
                g_ys[(size_t)(b*SEQ + t0 + s)*DI + h*HD + p] = y + xv*Dh;
            if (tid == 0)
                g_pi[(b*SEQ + t0 + s)*NH + h] = pi;
        }
        __syncthreads();
    }
    // final local state; physical layout unchanged (element n = q*16+i)
    size_t sb = ((size_t)(b*NH + h)*NCH + c)*(HD*NS);
    #pragma unroll
    for (int i = 0; i < 16; i++)
        g_S[sb + p*NS + q*16 + i] = hreg[i];
}

// ---------------- phase 2: chunk-state prefix (software-pipelined loads) ----------------
__global__ void __launch_bounds__(256) k_scan2() {
    int h = blockIdx.x, b = blockIdx.y;
    int tid = threadIdx.x;
    size_t base = (size_t)(b*NH + h)*NCH*(HD*NS);

    float Ac[NCH];
    #pragma unroll
    for (int c = 0; c < NCH; c++)
        Ac[c] = g_pi[(b*SEQ + c*CHUNK + CHUNK-1)*NH + h];

    float H[16], Sc[16];
    #pragma unroll
    for (int j = 0; j < 16; j++) H[j] = 0.f;
    #pragma unroll
    for (int j = 0; j < 16; j++) Sc[j] = g_S[base + tid*16 + j];

    #pragma unroll
    for (int c = 0; c < NCH; c++) {
        float Sn[16];
        if (c + 1 < NCH) {
            size_t noff = base + (size_t)(c+1)*(HD*NS) + tid*16;
            #pragma unroll
            for (int j = 0; j < 16; j++) Sn[j] = g_S[noff + j];
        }
        size_t off = base + (size_t)c*(HD*NS) + tid*16;
        #pragma unroll
        for (int j = 0; j < 16; j++) {
            float hp = H[j];
            g_S[off + j] = hp;
            H[j] = Ac[c]*hp + Sc[j];
        }
        #pragma unroll
        for (int j = 0; j < 16; j++) Sc[j] = Sn[j];
    }
}

// ---------------- phase 3: cross-chunk correction ----------------
__global__ void __launch_bounds__(256) k_scan3() {
    int h = blockIdx.x, b = blockIdx.y, c = blockIdx.z + 1;
    int tid = threadIdx.x;
    int pp = tid & 63, g = tid >> 6;

    __shared__ float sH[64][65];
    __shared__ float sC[16][64];
    __shared__ float spi[16];

    size_t hb = ((size_t)(b*NH + h)*NCH + c)*(HD*NS);
    for (int e = tid; e < HD*NS; e += 256)
        sH[e >> 6][e & 63] = g_S[hb + e];

    for (int tile = 0; tile < CHUNK/16; tile++) {
        int t0 = c*CHUNK + tile*16;
        __syncthreads();
        for (int i = tid; i < 16*64; i += 256) {
            int s = i >> 6, n = i & 63;
            sC[s][n] = g_xbc[(size_t)(b*SEQ + t0 + s)*CDIM + DI + NS + n];
        }
        if (tid < 16)
            spi[tid] = g_pi[(b*SEQ + t0 + tid)*NH + h];
        __syncthreads();
        #pragma unroll
        for (int u = 0; u < 4; u++) {
            int s = g*4 + u;
            float y = 0.f;
            #pragma unroll 16
            for (int n = 0; n < 64; n++)
                y += sC[s][n]*sH[pp][n];
            g_ys[(size_t)(b*SEQ + t0 + s)*DI + h*HD + pp] += spi[s]*y;
        }
    }
}

// ---------------- gate + RMSNorm -> fp16 pair g_a2 = [Ah | Al] ----------------
template<bool LUT0>
__global__ void k_gate(const float* __restrict__ nw, const int* __restrict__ ids) {
    int bt = blockIdx.x, tid = threadIdx.x;
    const float* ysr = g_ys + (size_t)bt*DI;
    const float* zr  = LUT0 ? (g_lut + (size_t)ids[bt]*DIP) : (g_zx + (size_t)bt*DIP);
    float v0 = ysr[tid]       * siluf(zr[tid]);
    float v1 = ysr[tid + 256] * siluf(zr[tid + 256]);
    __shared__ float red[256];
    red[tid] = v0*v0 + v1*v1;
    __syncthreads();
    for (int s = 128; s > 0; s >>= 1) {
        if (tid < s) red[tid] += red[tid + s];
        __syncthreads();
    }
    float scale = rsqrtf(red[0] * (1.f/DI) + 1e-5f);
    __half* a2 = g_a2 + (size_t)bt*(2*DI);
    float y0 = v0*scale*nw[tid];
    float y1 = v1*scale*nw[tid + 256];
    __half h0 = __float2half_rn(y0);
    __half l0 = __float2half_rn(y0 - __half2float(h0));
    __half h1 = __float2half_rn(y1);
    __half l1 = __float2half_rn(y1 - __half2float(h1));
    a2[tid] = h0;       a2[DI + tid] = l0;
    a2[tid + 256] = h1; a2[DI + tid + 256] = l1;
}

// ---------------- weight pair conversion: W2 = [Wf | Wf] ----------------
__global__ void k_cvtW(const float* __restrict__ W, __half* __restrict__ W2,
                       int N, int Npad, int K) {
    int idx = blockIdx.x*blockDim.x + threadIdx.x;
    if (idx >= Npad*K) return;
    int n = idx / K, k = idx % K;
    float w = (n < N) ? W[(size_t)n*K + k] : 0.f;
    __half hf = __float2half_rn(w);
    __half* row = W2 + (size_t)n*(2*K);
    row[k] = hf; row[K + k] = hf;
}

// ---------------- 3-stage pipelined tensor-core GEMM (mma.sync fp16, fp32 acc) ----------------
#define GBM 128
#define GBN 128
#define GBK 32
#define STG 3
#define LDA (GBK+8)
#define SMEM_MMA (STG*2*GBM*LDA*2)

template<int RESID_MODE, bool X2OUT>
__global__ void __launch_bounds__(256) k_mma(
        const __half* __restrict__ A,
        const __half* __restrict__ W,
        const float* __restrict__ R,
        const int* __restrict__ ids,
        const float* __restrict__ emb,
        float* __restrict__ C,
        __half* __restrict__ X2,
        int N, int Kp, int ldc)
{
    extern __shared__ __half smp[];
    __half* Asm = smp;
    __half* Wsm = smp + STG*GBM*LDA;

    int tid = threadIdx.x;
    int warp = tid >> 5, lane = tid & 31;
    int wm = warp >> 2, wn = warp & 3;
    int m0 = blockIdx.y * GBM;
    int n0 = blockIdx.x * GBN;

    float acc[4][4][4];
    #pragma unroll
    for (int i = 0; i < 4; i++)
        #pragma unroll
        for (int j = 0; j < 4; j++)
            #pragma unroll
            for (int e = 0; e < 4; e++) acc[i][j][e] = 0.f;

    int nk = Kp / GBK;

    auto load_stage = [&](int st, int k0) {
        __half* as = Asm + st*GBM*LDA;
        __half* ws = Wsm + st*GBM*LDA;
        #pragma unroll
        for (int u = 0; u < 2; u++) {
            int idx = tid + u*256;
            int r = idx >> 2, kc = (idx & 3)*8;
            unsigned da = (unsigned)__cvta_generic_to_shared(as + r*LDA + kc);
            asm volatile("cp.async.cg.shared.global [%0], [%1], 16;\n"
                :: "r"(da), "l"(A + (size_t)(m0 + r)*Kp + k0 + kc));
            unsigned dw = (unsigned)__cvta_generic_to_shared(ws + r*LDA + kc);
            asm volatile("cp.async.cg.shared.global [%0], [%1], 16;\n"
                :: "r"(dw), "l"(W + (size_t)(n0 + r)*Kp + k0 + kc));
        }
    };

    load_stage(0, 0);
    cp_commit();
    load_stage(1, GBK);
    cp_commit();

    for (int it = 0; it < nk; it++) {
        cp_wait<1>();
        __syncthreads();
        if (it + 2 < nk) {
            load_stage((it + 2) % STG, (it + 2)*GBK);
            cp_commit();
        } else {
            cp_commit();
        }
        int st = it % STG;
        __half* as = Asm + st*GBM*LDA;
        __half* ws = Wsm + st*GBM*LDA;

        #pragma unroll
        for (int kk = 0; kk < GBK; kk += 16) {
            unsigned af[4][4];
            #pragma unroll
            for (int i = 0; i < 4; i++) {
                int row = wm*64 + i*16 + (lane & 15);
                int col = kk + ((lane >> 4) << 3);
                unsigned addr = (unsigned)__cvta_generic_to_shared(as + row*LDA + col);
                asm volatile("ldmatrix.sync.aligned.m8n8.x4.shared.b16 {%0,%1,%2,%3}, [%4];\n"
                    : "=r"(af[i][0]), "=r"(af[i][1]), "=r"(af[i][2]), "=r"(af[i][3]) : "r"(addr));
            }
            unsigned bfm[2][4];
            #pragma unroll
            for (int g = 0; g < 2; g++) {
                int row = wn*32 + g*16 + (lane & 15);
                int col = kk + ((lane >> 4) << 3);
                unsigned addr = (unsigned)__cvta_generic_to_shared(ws + row*LDA + col);
                asm volatile("ldmatrix.sync.aligned.m8n8.x4.shared.b16 {%0,%1,%2,%3}, [%4];\n"
                    : "=r"(bfm[g][0]), "=r"(bfm[g][1]), "=r"(bfm[g][2]), "=r"(bfm[g][3]) : "r"(addr));
            }
            #pragma unroll
            for (int i = 0; i < 4; i++) {
                #pragma unroll
                for (int g = 0; g < 2; g++) {
                    #pragma unroll
                    for (int s = 0; s < 2; s++) {
                        int j = g*2 + s;
                        asm volatile(
                            "mma.sync.aligned.m16n8k16.row.col.f32.f16.f16.f32 "
                            "{%0,%1,%2,%3}, {%4,%5,%6,%7}, {%8,%9}, {%0,%1,%2,%3};\n"
                            : "+f"(acc[i][j][0]), "+f"(acc[i][j][1]),
                              "+f"(acc[i][j][2]), "+f"(acc[i][j][3])
                            : "r"(af[i][0]), "r"(af[i][1]), "r"(af[i][2]), "r"(af[i][3]),
                              "r"(bfm[g][s]), "r"(bfm[g][s+2]));
                    }
                }
            }
        }
    }

    // epilogue
    #pragma unroll
    for (int i = 0; i < 4; i++) {
        #pragma unroll
        for (int half_ = 0; half_ < 2; half_++) {
            int m = m0 + wm*64 + i*16 + (lane >> 2) + half_*8;
            const float* rrow = nullptr;
            if (RESID_MODE == 1) rrow = R + (size_t)m*ldc;
            if (RESID_MODE == 2) rrow = emb + (size_t)ids[m]*DM;
            #pragma unroll
            for (int j = 0; j < 4; j++) {
                int ncol = n0 + wn*32 + j*8 + (lane & 3)*2;
                #pragma unroll
                for (int e = 0; e < 2; e++) {
                    int n = ncol + e;
                    if (n < N) {
                        float v = acc[i][j][half_*2 + e];
                        if (RESID_MODE) v += rrow[n];
                        C[(size_t)m*ldc + n] = v;
                        if (X2OUT) {
                            __half hh = __float2half_rn(v);
                            __half ll = __float2half_rn(v - __half2float(hh));
                            __half* row = X2 + (size_t)m*(2*N);
                            row[n] = hh; row[N + n] = ll;
                        }
                    }
                }
            }
        }
    }
}

// ---------------- pooling ----------------
__global__ void k_pool1() {
    int seg = blockIdx.x, b = blockIdx.y, d = threadIdx.x;
    float sum = 0.f, mx = -INFINITY;
    for (int i = 0; i < 64; i++) {
        float v = g_x[(size_t)(b*SEQ + seg*64 + i)*DM + d];
        sum += v; mx = fmaxf(mx, v);
    }
    g_psum[(b*16 + seg)*DM + d] = sum;
    g_pmax[(b*16 + seg)*DM + d] = mx;
}
__global__ void k_pool2() {
    int b = blockIdx.x, d = threadIdx.x;
    float sum = 0.f, mx = -INFINITY;
    for (int s = 0; s < 16; s++) {
        sum += g_psum[(b*16 + s)*DM + d];
        mx = fmaxf(mx, g_pmax[(b*16 + s)*DM + d]);
    }
    g_pooled[b*DM + d] = (sum*(1.f/SEQ) + mx)*0.5f;
}

// ---------------- classification head ----------------
__global__ void k_head(const float* __restrict__ pw, const float* __restrict__ pb,
                       const float* __restrict__ c1w, const float* __restrict__ c1b,
                       const float* __restrict__ c2w, const float* __restrict__ c2b,
                       float* __restrict__ out) {
    int b = blockIdx.x, tid = threadIdx.x;
    __shared__ float sp[DM], s1[DM], s2[128];
    sp[tid] = g_pooled[b*DM + tid];
    __syncthreads();
    {
        float acc = pb[tid];
        const float* wr = pw + (size_t)tid*DM;
        for (int d = 0; d < DM; d++) acc += sp[d]*wr[d];
        s1[tid] = geluf(acc);
    }
    __syncthreads();
    if (tid < 128) {
        float acc = c1b[tid];
        const float* wr = c1w + (size_t)tid*DM;
        for (int d = 0; d < DM; d++) acc += s1[d]*wr[d];
        s2[tid] = geluf(acc);
    }
    __syncthreads();
    if (tid < 2) {
        float acc = c2b[tid];
        const float* wr = c2w + tid*128;
        for (int d = 0; d < 128; d++) acc += s2[d]*wr[d];
        out[b*2 + tid] = acc;
    }
}

// ---------------- launch ----------------
extern "C" void kernel_launch(void* const* d_in, const int* in_sizes, int n_in,
                              void* d_out, int out_size) {
    const int*   ids  = (const int*)  d_in[0];
    const float* emb  = (const float*)d_in[1];
    const float* inw  = (const float*)d_in[2];
    const float* cw   = (const float*)d_in[3];
    const float* cb   = (const float*)d_in[4];
    const float* dtb  = (const float*)d_in[5];
    const float* alog = (const float*)d_in[6];
    const float* Dv   = (const float*)d_in[7];
    const float* nw   = (const float*)d_in[8];
    const float* ow   = (const float*)d_in[9];
    const float* pw   = (const float*)d_in[10];
    const float* pb   = (const float*)d_in[11];
    const float* c1w  = (const float*)d_in[12];
    const float* c1b  = (const float*)d_in[13];
    const float* c2w  = (const float*)d_in[14];
    const float* c2b  = (const float*)d_in[15];
    float* out = (float*)d_out;

    float *px, *pzx;
    __half *pa2, *px2, *pw2a, *pw2b;
    cudaGetSymbolAddress((void**)&px,   g_x);
    cudaGetSymbolAddress((void**)&pzx,  g_zx);
    cudaGetSymbolAddress((void**)&pa2,  g_a2);
    cudaGetSymbolAddress((void**)&px2,  g_x2);
    cudaGetSymbolAddress((void**)&pw2a, g_w2a);
    cudaGetSymbolAddress((void**)&pw2b, g_w2b);

    cudaFuncSetAttribute(k_mma<2, true>,
        cudaFuncAttributeMaxDynamicSharedMemorySize, SMEM_MMA);
    cudaFuncSetAttribute(k_mma<0, false>,
        cudaFuncAttributeMaxDynamicSharedMemorySize, SMEM_MMA);
    cudaFuncSetAttribute(k_mma<1, false>,
        cudaFuncAttributeMaxDynamicSharedMemorySize, SMEM_MMA);

    // ---- layer 0 (launch #4 = k_scan1 for profiling) ----
    k_cvtW<<<(NPAD_IN*DM + 255)/256, 256>>>(inw + (size_t)DIP*DM, pw2a, DIP, NPAD_IN, DM);
    k_lut<<<(DIP + 255)/256, 256>>>(emb, inw);
    k_conv<true><<<NTOK, 256>>>(cw, cb, dtb, alog, ids);
    k_scan1<<<dim3(NH, BATCH, NCH), 256>>>(Dv);
    k_scan2<<<dim3(NH, BATCH), 256>>>();
    k_scan3<<<dim3(NH, BATCH, NCH-1), 256>>>();
    k_gate<true><<<NTOK, 256>>>(nw, ids);
    k_cvtW<<<(DM*DI + 255)/256, 256>>>(ow, pw2b, DM, DM, DI);
    k_mma<2, true><<<dim3(DM/GBN, NTOK/GBM), 256, SMEM_MMA>>>(
        pa2, pw2b, nullptr, ids, emb, px, px2, DM, 2*DI, DM);

    // ---- layer 1 ----
    k_mma<0, false><<<dim3(NPAD_IN/GBN, NTOK/GBM), 256, SMEM_MMA>>>(
        px2, pw2a, nullptr, nullptr, nullptr, pzx, nullptr, DIP, 2*DM, DIP);
    k_conv<false><<<NTOK, 256>>>(cw + (size_t)CDIM*4, cb + CDIM, dtb + NH, alog + NH, ids);
    k_scan1<<<dim3(NH, BATCH, NCH), 256>>>(Dv + NH);
    k_scan2<<<dim3(NH, BATCH), 256>>>();
    k_scan3<<<dim3(NH, BATCH, NCH-1), 256>>>();
    k_gate<false><<<NTOK, 256>>>(nw + DI, ids);
    k_cvtW<<<(DM*DI + 255)/256, 256>>>(ow + (size_t)DM*DI, pw2b, DM, DM, DI);
    k_mma<1, false><<<dim3(DM/GBN, NTOK/GBM), 256, SMEM_MMA>>>(
        pa2, pw2b, px, nullptr, nullptr, px, nullptr, DM, 2*DI, DM);

    k_pool1<<<dim3(16, BATCH), DM>>>();
    k_pool2<<<BATCH, DM>>>();
    k_head<<<BATCH, DM>>>(pw, pb, c1w, c1b, c2w, c2b, out);
}

// round 14
// speedup vs baseline: 1.2152x; 1.2152x over previous
#include <cuda_runtime.h>
#include <cuda_fp16.h>
#include <cstdint>
#include <math.h>

#define BATCH 8
#define SEQ   1024
#define DM    256
#define DI    512
#define NH    8
#define HD    64
#define NS    64
#define CDIM  640
#define DIP   1160
#define NTOK  (BATCH*SEQ)   // 8192
#define NPAD_IN 1280        // 10*128
#define NCH   16
#define CHUNK 64            // SEQ / NCH

// ---------------- device scratch ----------------
__device__ __align__(16) float g_x[NTOK*DM];
__device__ __align__(16) float g_zx[NTOK*DIP];
__device__ __align__(16) float g_xbc[NTOK*CDIM];
__device__ float g_dt[NTOK*NH];
__device__ float g_dA[NTOK*NH];
__device__ float g_pi[NTOK*NH];
__device__ __align__(16) float g_S[(size_t)BATCH*NH*NCH*HD*NS];
__device__ __align__(16) float g_ys[NTOK*DI];
__device__ __align__(16) float g_lut[8*DIP];
__device__ float g_psum[BATCH*16*DM];
__device__ float g_pmax[BATCH*16*DM];
__device__ float g_pooled[BATCH*DM];
// fp16 2-term GEMM operands: A2 = [Ah | Al], W2 = [Wf | Wf]
__device__ __align__(16) __half g_a2[NTOK*2*DI];
__device__ __align__(16) __half g_x2[NTOK*2*DM];
__device__ __align__(16) __half g_w2a[NPAD_IN*2*DM];
__device__ __align__(16) __half g_w2b[DM*2*DI];

__device__ __forceinline__ float siluf(float x) { return x / (1.f + expf(-x)); }
__device__ __forceinline__ float geluf(float x) { return 0.5f * x * (1.f + erff(x * 0.7071067811865476f)); }

template<int N> __device__ __forceinline__ void cp_wait() {
    asm volatile("cp.async.wait_group %0;\n" :: "n"(N));
}
__device__ __forceinline__ void cp_commit() {
    asm volatile("cp.async.commit_group;\n");
}

// ---------------- layer-0 in_proj LUT ----------------
__global__ void k_lut(const float* __restrict__ emb, const float* __restrict__ W) {
    __shared__ float se[8*DM];
    for (int i = threadIdx.x; i < 8*DM; i += blockDim.x) se[i] = emb[i];
    __syncthreads();
    int e = blockIdx.x*blockDim.x + threadIdx.x;
    if (e >= DIP) return;
    float acc[8] = {0.f,0.f,0.f,0.f,0.f,0.f,0.f,0.f};
    const float* wr = W + (size_t)e*DM;
    for (int d = 0; d < DM; d++) {
        float wv = wr[d];
        #pragma unroll
        for (int v = 0; v < 8; v++) acc[v] += wv * se[v*DM + d];
    }
    #pragma unroll
    for (int v = 0; v < 8; v++) g_lut[(size_t)v*DIP + e] = acc[v];
}

// ---------------- conv4 + silu + softplus(dt) + dA ----------------
template<bool LUT0>
__global__ void k_conv(const float* __restrict__ cw, const float* __restrict__ cb,
                       const float* __restrict__ dtb, const float* __restrict__ Alog,
                       const int* __restrict__ ids) {
    int bt = blockIdx.x;
    int t  = bt & (SEQ-1);
    const float* rows[4];
    #pragma unroll
    for (int k = 0; k < 4; k++) {
        int tt = t - 3 + k;
        if (tt >= 0) {
            int src = bt - 3 + k;
            rows[k] = LUT0 ? (g_lut + (size_t)ids[src]*DIP) : (g_zx + (size_t)src*DIP);
        } else rows[k] = nullptr;
    }
    for (int c = threadIdx.x; c < CDIM; c += blockDim.x) {
        float acc = cb[c];
        #pragma unroll
        for (int k = 0; k < 4; k++)
            if (rows[k]) acc += rows[k][DI + c] * cw[c*4 + k];
        g_xbc[(size_t)bt*CDIM + c] = siluf(acc);
    }
    if (threadIdx.x < NH) {
        int h = threadIdx.x;
        float xr = (LUT0 ? g_lut[(size_t)ids[bt]*DIP + DI + CDIM + h]
                         : g_zx[(size_t)bt*DIP + DI + CDIM + h]) + dtb[h];
        float dtv = (xr > 20.f) ? xr : log1pf(expf(xr));
        g_dt[bt*NH + h] = dtv;
        g_dA[bt*NH + h] = expf(dtv * (-expf(Alog[h])));
    }
}

// ---------------- phase 1: local chunk scan (exact R11 inner loop; NCH=16) ----------------
__global__ void __launch_bounds__(256) k_scan1(const float* __restrict__ Dp) {
    int h = blockIdx.x, b = blockIdx.y, c = blockIdx.z;
    int tid = threadIdx.x;
    int p = tid >> 2, q = tid & 3;
    float Dh = Dp[h];
    float hreg[16];
    #pragma unroll
    for (int i = 0; i < 16; i++) hreg[i] = 0.f;
    float pi = 1.f;

    __shared__ float sx[16][64], sB[16][64], sC[16][64];
    __shared__ float sdt[16], sdA[16];

    int tbase = c*CHUNK;
    for (int tile = 0; tile < CHUNK/16; tile++) {
        int t0 = tbase + tile*16;
        for (int i = tid; i < 16*64; i += 256) {
            int s = i >> 6, j = i & 63;
            const float* row = g_xbc + (size_t)(b*SEQ + t0 + s)*CDIM;
            sx[s][j] = row[h*HD + j];
            sB[s][j] = row[DI + j];
            sC[s][j] = row[DI + NS + j];
        }
        if (tid < 16) {
            sdt[tid] = g_dt[(b*SEQ + t0 + tid)*NH + h];
            sdA[tid] = g_dA[(b*SEQ + t0 + tid)*NH + h];
        }
        __syncthreads();
        #pragma unroll 4
        for (int s = 0; s < 16; s++) {
            float da  = sdA[s];
            pi *= da;
            float xv  = sx[s][p];
            float dtx = sdt[s] * xv;
            float y = 0.f;
            #pragma unroll
            for (int i = 0; i < 16; i++) {
                int n = q + 4*i;
                hreg[i] = hreg[i]*da + dtx*sB[s][n];
                y += hreg[i]*sC[s][n];
            }
            y += __shfl_xor_sync(0xffffffffu, y, 1);
            y += __shfl_xor_sync(0xffffffffu, y, 2);
            if (q == 0)
                g_ys[(size_t)(b*SEQ + t0 + s)*DI + h*HD + p] = y + xv*Dh;
            if (tid == 0)
                g_pi[(b*SEQ + t0 + s)*NH + h] = pi;
        }
        __syncthreads();
    }
    size_t sb = ((size_t)(b*NH + h)*NCH + c)*(HD*NS);
    #pragma unroll
    for (int i = 0; i < 16; i++)
        g_S[sb + p*NS + q + 4*i] = hreg[i];
}

// ---------------- phase 2: chunk-state prefix (software-pipelined loads) ----------------
__global__ void __launch_bounds__(256) k_scan2() {
    int h = blockIdx.x, b = blockIdx.y;
    int tid = threadIdx.x;
    size_t base = (size_t)(b*NH + h)*NCH*(HD*NS);

    float Ac[NCH];
    #pragma unroll
    for (int c = 0; c < NCH; c++)
        Ac[c] = g_pi[(b*SEQ + c*CHUNK + CHUNK-1)*NH + h];

    float H[16], Sc[16];
    #pragma unroll
    for (int j = 0; j < 16; j++) H[j] = 0.f;
    #pragma unroll
    for (int j = 0; j < 16; j++) Sc[j] = g_S[base + tid*16 + j];

    #pragma unroll
    for (int c = 0; c < NCH; c++) {
        float Sn[16];
        if (c + 1 < NCH) {
            size_t noff = base + (size_t)(c+1)*(HD*NS) + tid*16;
            #pragma unroll
            for (int j = 0; j < 16; j++) Sn[j] = g_S[noff + j];
        }
        size_t off = base + (size_t)c*(HD*NS) + tid*16;
        #pragma unroll
        for (int j = 0; j < 16; j++) {
            float hp = H[j];
            g_S[off + j] = hp;
            H[j] = Ac[c]*hp + Sc[j];
        }
        #pragma unroll
        for (int j = 0; j < 16; j++) Sc[j] = Sn[j];
    }
}

// ---------------- phase 3: cross-chunk correction ----------------
__global__ void __launch_bounds__(256) k_scan3() {
    int h = blockIdx.x, b = blockIdx.y, c = blockIdx.z + 1;
    int tid = threadIdx.x;
    int pp = tid & 63, g = tid >> 6;

    __shared__ float sH[64][65];
    __shared__ float sC[16][64];
    __shared__ float spi[16];

    size_t hb = ((size_t)(b*NH + h)*NCH + c)*(HD*NS);
    for (int e = tid; e < HD*NS; e += 256)
        sH[e >> 6][e & 63] = g_S[hb + e];

    for (int tile = 0; tile < CHUNK/16; tile++) {
        int t0 = c*CHUNK + tile*16;
        __syncthreads();
        for (int i = tid; i < 16*64; i += 256) {
            int s = i >> 6, n = i & 63;
            sC[s][n] = g_xbc[(size_t)(b*SEQ + t0 + s)*CDIM + DI + NS + n];
        }
        if (tid < 16)
            spi[tid] = g_pi[(b*SEQ + t0 + tid)*NH + h];
        __syncthreads();
        #pragma unroll
        for (int u = 0; u < 4; u++) {
            int s = g*4 + u;
            float y = 0.f;
            #pragma unroll 16
            for (int n = 0; n < 64; n++)
                y += sC[s][n]*sH[pp][n];
            g_ys[(size_t)(b*SEQ + t0 + s)*DI + h*HD + pp] += spi[s]*y;
        }
    }
}

// ---------------- gate + RMSNorm -> fp16 pair g_a2 = [Ah | Al] ----------------
template<bool LUT0>
__global__ void k_gate(const float* __restrict__ nw, const int* __restrict__ ids) {
    int bt = blockIdx.x, tid = threadIdx.x;
    const float* ysr = g_ys + (size_t)bt*DI;
    const float* zr  = LUT0 ? (g_lut + (size_t)ids[bt]*DIP) : (g_zx + (size_t)bt*DIP);
    float v0 = ysr[tid]       * siluf(zr[tid]);
    float v1 = ysr[tid + 256] * siluf(zr[tid + 256]);
    __shared__ float red[256];
    red[tid] = v0*v0 + v1*v1;
    __syncthreads();
    for (int s = 128; s > 0; s >>= 1) {
        if (tid < s) red[tid] += red[tid + s];
        __syncthreads();
    }
    float scale = rsqrtf(red[0] * (1.f/DI) + 1e-5f);
    __half* a2 = g_a2 + (size_t)bt*(2*DI);
    float y0 = v0*scale*nw[tid];
    float y1 = v1*scale*nw[tid + 256];
    __half h0 = __float2half_rn(y0);
    __half l0 = __float2half_rn(y0 - __half2float(h0));
    __half h1 = __float2half_rn(y1);
    __half l1 = __float2half_rn(y1 - __half2float(h1));
    a2[tid] = h0;       a2[DI + tid] = l0;
    a2[tid + 256] = h1; a2[DI + tid + 256] = l1;
}

// ---------------- weight pair conversion: W2 = [Wf | Wf] ----------------
__global__ void k_cvtW(const float* __restrict__ W, __half* __restrict__ W2,
                       int N, int Npad, int K) {
    int idx = blockIdx.x*blockDim.x + threadIdx.x;
    if (idx >= Npad*K) return;
    int n = idx / K, k = idx % K;
    float w = (n < N) ? W[(size_t)n*K + k] : 0.f;
    __half hf = __float2half_rn(w);
    __half* row = W2 + (size_t)n*(2*K);
    row[k] = hf; row[K + k] = hf;
}

// ---------------- 3-stage pipelined tensor-core GEMM (mma.sync fp16, fp32 acc) ----------------
#define GBM 128
#define GBN 128
#define GBK 32
#define STG 3
#define LDA (GBK+8)
#define SMEM_MMA (STG*2*GBM*LDA*2)

template<int RESID_MODE, bool X2OUT>
__global__ void __launch_bounds__(256) k_mma(
        const __half* __restrict__ A,
        const __half* __restrict__ W,
        const float* __restrict__ R,
        const int* __restrict__ ids,
        const float* __restrict__ emb,
        float* __restrict__ C,
        __half* __restrict__ X2,
        int N, int Kp, int ldc)
{
    extern __shared__ __half smp[];
    __half* Asm = smp;
    __half* Wsm = smp + STG*GBM*LDA;

    int tid = threadIdx.x;
    int warp = tid >> 5, lane = tid & 31;
    int wm = warp >> 2, wn = warp & 3;
    int m0 = blockIdx.y * GBM;
    int n0 = blockIdx.x * GBN;

    float acc[4][4][4];
    #pragma unroll
    for (int i = 0; i < 4; i++)
        #pragma unroll
        for (int j = 0; j < 4; j++)
            #pragma unroll
            for (int e = 0; e < 4; e++) acc[i][j][e] = 0.f;

    int nk = Kp / GBK;

    auto load_stage = [&](int st, int k0) {
        __half* as = Asm + st*GBM*LDA;
        __half* ws = Wsm + st*GBM*LDA;
        #pragma unroll
        for (int u = 0; u < 2; u++) {
            int idx = tid + u*256;
            int r = idx >> 2, kc = (idx & 3)*8;
            unsigned da = (unsigned)__cvta_generic_to_shared(as + r*LDA + kc);
            asm volatile("cp.async.cg.shared.global [%0], [%1], 16;\n"
                :: "r"(da), "l"(A + (size_t)(m0 + r)*Kp + k0 + kc));
            unsigned dw = (unsigned)__cvta_generic_to_shared(ws + r*LDA + kc);
            asm volatile("cp.async.cg.shared.global [%0], [%1], 16;\n"
                :: "r"(dw), "l"(W + (size_t)(n0 + r)*Kp + k0 + kc));
        }
    };

    load_stage(0, 0);
    cp_commit();
    load_stage(1, GBK);
    cp_commit();

    for (int it = 0; it < nk; it++) {
        cp_wait<1>();
        __syncthreads();
        if (it + 2 < nk) {
            load_stage((it + 2) % STG, (it + 2)*GBK);
            cp_commit();
        } else {
            cp_commit();
        }
        int st = it % STG;
        __half* as = Asm + st*GBM*LDA;
        __half* ws = Wsm + st*GBM*LDA;

        #pragma unroll
        for (int kk = 0; kk < GBK; kk += 16) {
            unsigned af[4][4];
            #pragma unroll
            for (int i = 0; i < 4; i++) {
                int row = wm*64 + i*16 + (lane & 15);
                int col = kk + ((lane >> 4) << 3);
                unsigned addr = (unsigned)__cvta_generic_to_shared(as + row*LDA + col);
                asm volatile("ldmatrix.sync.aligned.m8n8.x4.shared.b16 {%0,%1,%2,%3}, [%4];\n"
                    : "=r"(af[i][0]), "=r"(af[i][1]), "=r"(af[i][2]), "=r"(af[i][3]) : "r"(addr));
            }
            unsigned bfm[2][4];
            #pragma unroll
            for (int g = 0; g < 2; g++) {
                int row = wn*32 + g*16 + (lane & 15);
                int col = kk + ((lane >> 4) << 3);
                unsigned addr = (unsigned)__cvta_generic_to_shared(ws + row*LDA + col);
                asm volatile("ldmatrix.sync.aligned.m8n8.x4.shared.b16 {%0,%1,%2,%3}, [%4];\n"
                    : "=r"(bfm[g][0]), "=r"(bfm[g][1]), "=r"(bfm[g][2]), "=r"(bfm[g][3]) : "r"(addr));
            }
            #pragma unroll
            for (int i = 0; i < 4; i++) {
                #pragma unroll
                for (int g = 0; g < 2; g++) {
                    #pragma unroll
                    for (int s = 0; s < 2; s++) {
                        int j = g*2 + s;
                        asm volatile(
                            "mma.sync.aligned.m16n8k16.row.col.f32.f16.f16.f32 "
                            "{%0,%1,%2,%3}, {%4,%5,%6,%7}, {%8,%9}, {%0,%1,%2,%3};\n"
                            : "+f"(acc[i][j][0]), "+f"(acc[i][j][1]),
                              "+f"(acc[i][j][2]), "+f"(acc[i][j][3])
                            : "r"(af[i][0]), "r"(af[i][1]), "r"(af[i][2]), "r"(af[i][3]),
                              "r"(bfm[g][s]), "r"(bfm[g][s+2]));
                    }
                }
            }
        }
    }

    // epilogue
    #pragma unroll
    for (int i = 0; i < 4; i++) {
        #pragma unroll
        for (int half_ = 0; half_ < 2; half_++) {
            int m = m0 + wm*64 + i*16 + (lane >> 2) + half_*8;
            const float* rrow = nullptr;
            if (RESID_MODE == 1) rrow = R + (size_t)m*ldc;
            if (RESID_MODE == 2) rrow = emb + (size_t)ids[m]*DM;
            #pragma unroll
            for (int j = 0; j < 4; j++) {
                int ncol = n0 + wn*32 + j*8 + (lane & 3)*2;
                #pragma unroll
                for (int e = 0; e < 2; e++) {
                    int n = ncol + e;
                    if (n < N) {
                        float v = acc[i][j][half_*2 + e];
                        if (RESID_MODE) v += rrow[n];
                        C[(size_t)m*ldc + n] = v;
                        if (X2OUT) {
                            __half hh = __float2half_rn(v);
                            __half ll = __float2half_rn(v - __half2float(hh));
                            __half* row = X2 + (size_t)m*(2*N);
                            row[n] = hh; row[N + n] = ll;
                        }
                    }
                }
            }
        }
    }
}

// ---------------- pooling ----------------
__global__ void k_pool1() {
    int seg = blockIdx.x, b = blockIdx.y, d = threadIdx.x;
    float sum = 0.f, mx = -INFINITY;
    for (int i = 0; i < 64; i++) {
        float v = g_x[(size_t)(b*SEQ + seg*64 + i)*DM + d];
        sum += v; mx = fmaxf(mx, v);
    }
    g_psum[(b*16 + seg)*DM + d] = sum;
    g_pmax[(b*16 + seg)*DM + d] = mx;
}
__global__ void k_pool2() {
    int b = blockIdx.x, d = threadIdx.x;
    float sum = 0.f, mx = -INFINITY;
    for (int s = 0; s < 16; s++) {
        sum += g_psum[(b*16 + s)*DM + d];
        mx = fmaxf(mx, g_pmax[(b*16 + s)*DM + d]);
    }
    g_pooled[b*DM + d] = (sum*(1.f/SEQ) + mx)*0.5f;
}

// ---------------- classification head ----------------
__global__ void k_head(const float* __restrict__ pw, const float* __restrict__ pb,
                       const float* __restrict__ c1w, const float* __restrict__ c1b,
                       const float* __restrict__ c2w, const float* __restrict__ c2b,
                       float* __restrict__ out) {
    int b = blockIdx.x, tid = threadIdx.x;
    __shared__ float sp[DM], s1[DM], s2[128];
    sp[tid] = g_pooled[b*DM + tid];
    __syncthreads();
    {
        float acc = pb[tid];
        const float* wr = pw + (size_t)tid*DM;
        for (int d = 0; d < DM; d++) acc += sp[d]*wr[d];
        s1[tid] = geluf(acc);
    }
    __syncthreads();
    if (tid < 128) {
        float acc = c1b[tid];
        const float* wr = c1w + (size_t)tid*DM;
        for (int d = 0; d < DM; d++) acc += s1[d]*wr[d];
        s2[tid] = geluf(acc);
    }
    __syncthreads();
    if (tid < 2) {
        float acc = c2b[tid];
        const float* wr = c2w + tid*128;
        for (int d = 0; d < 128; d++) acc += s2[d]*wr[d];
        out[b*2 + tid] = acc;
    }
}

// ---------------- launch ----------------
extern "C" void kernel_launch(void* const* d_in, const int* in_sizes, int n_in,
                              void* d_out, int out_size) {
    const int*   ids  = (const int*)  d_in[0];
    const float* emb  = (const float*)d_in[1];
    const float* inw  = (const float*)d_in[2];
    const float* cw   = (const float*)d_in[3];
    const float* cb   = (const float*)d_in[4];
    const float* dtb  = (const float*)d_in[5];
    const float* alog = (const float*)d_in[6];
    const float* Dv   = (const float*)d_in[7];
    const float* nw   = (const float*)d_in[8];
    const float* ow   = (const float*)d_in[9];
    const float* pw   = (const float*)d_in[10];
    const float* pb   = (const float*)d_in[11];
    const float* c1w  = (const float*)d_in[12];
    const float* c1b  = (const float*)d_in[13];
    const float* c2w  = (const float*)d_in[14];
    const float* c2b  = (const float*)d_in[15];
    float* out = (float*)d_out;

    float *px, *pzx;
    __half *pa2, *px2, *pw2a, *pw2b;
    cudaGetSymbolAddress((void**)&px,   g_x);
    cudaGetSymbolAddress((void**)&pzx,  g_zx);
    cudaGetSymbolAddress((void**)&pa2,  g_a2);
    cudaGetSymbolAddress((void**)&px2,  g_x2);
    cudaGetSymbolAddress((void**)&pw2a, g_w2a);
    cudaGetSymbolAddress((void**)&pw2b, g_w2b);

    cudaFuncSetAttribute(k_mma<2, true>,
        cudaFuncAttributeMaxDynamicSharedMemorySize, SMEM_MMA);
    cudaFuncSetAttribute(k_mma<0, false>,
        cudaFuncAttributeMaxDynamicSharedMemorySize, SMEM_MMA);
    cudaFuncSetAttribute(k_mma<1, false>,
        cudaFuncAttributeMaxDynamicSharedMemorySize, SMEM_MMA);

    // ---- layer 0 (launch #4 = k_scan1 for profiling) ----
    k_cvtW<<<(NPAD_IN*DM + 255)/256, 256>>>(inw + (size_t)DIP*DM, pw2a, DIP, NPAD_IN, DM);
    k_lut<<<(DIP + 255)/256, 256>>>(emb, inw);
    k_conv<true><<<NTOK, 256>>>(cw, cb, dtb, alog, ids);
    k_scan1<<<dim3(NH, BATCH, NCH), 256>>>(Dv);
    k_scan2<<<dim3(NH, BATCH), 256>>>();
    k_scan3<<<dim3(NH, BATCH, NCH-1), 256>>>();
    k_gate<true><<<NTOK, 256>>>(nw, ids);
    k_cvtW<<<(DM*DI + 255)/256, 256>>>(ow, pw2b, DM, DM, DI);
    k_mma<2, true><<<dim3(DM/GBN, NTOK/GBM), 256, SMEM_MMA>>>(
        pa2, pw2b, nullptr, ids, emb, px, px2, DM, 2*DI, DM);

    // ---- layer 1 ----
    k_mma<0, false><<<dim3(NPAD_IN/GBN, NTOK/GBM), 256, SMEM_MMA>>>(
        px2, pw2a, nullptr, nullptr, nullptr, pzx, nullptr, DIP, 2*DM, DIP);
    k_conv<false><<<NTOK, 256>>>(cw + (size_t)CDIM*4, cb + CDIM, dtb + NH, alog + NH, ids);
    k_scan1<<<dim3(NH, BATCH, NCH), 256>>>(Dv + NH);
    k_scan2<<<dim3(NH, BATCH), 256>>>();
    k_scan3<<<dim3(NH, BATCH, NCH-1), 256>>>();
    k_gate<false><<<NTOK, 256>>>(nw + DI, ids);
    k_cvtW<<<(DM*DI + 255)/256, 256>>>(ow + (size_t)DM*DI, pw2b, DM, DM, DI);
    k_mma<1, false><<<dim3(DM/GBN, NTOK/GBM), 256, SMEM_MMA>>>(
        pa2, pw2b, px, nullptr, nullptr, px, nullptr, DM, 2*DI, DM);

    k_pool1<<<dim3(16, BATCH), DM>>>();
    k_pool2<<<BATCH, DM>>>();
    k_head<<<BATCH, DM>>>(pw, pb, c1w, c1b, c2w, c2b, out);
}

// round 15
// speedup vs baseline: 1.2191x; 1.0032x over previous
#include <cuda_runtime.h>
#include <cuda_fp16.h>
#include <cstdint>
#include <math.h>

#define BATCH 8
#define SEQ   1024
#define DM    256
#define DI    512
#define NH    8
#define HD    64
#define NS    64
#define CDIM  640
#define DIP   1160
#define NTOK  (BATCH*SEQ)   // 8192
#define NPAD_IN 1280        // 10*128
#define NCH   16
#define CHUNK 64            // SEQ / NCH

// ---------------- device scratch ----------------
__device__ __align__(16) float g_x[NTOK*DM];
__device__ __align__(16) float g_zx[NTOK*DIP];
__device__ __align__(16) float g_xbc[NTOK*CDIM];
__device__ float g_dt[NTOK*NH];
__device__ float g_dA[NTOK*NH];
__device__ float g_pi[NTOK*NH];
__device__ __align__(16) float g_S[(size_t)BATCH*NH*NCH*HD*NS];
__device__ __align__(16) float g_ys[NTOK*DI];
__device__ __align__(16) float g_lut[8*DIP];
__device__ float g_psum[BATCH*16*DM];
__device__ float g_pmax[BATCH*16*DM];
__device__ float g_pooled[BATCH*DM];
// fp16 2-term GEMM operands: A2 = [Ah | Al], W2 = [Wf | Wf]
__device__ __align__(16) __half g_a2[NTOK*2*DI];
__device__ __align__(16) __half g_x2[NTOK*2*DM];
__device__ __align__(16) __half g_w2a[NPAD_IN*2*DM];
__device__ __align__(16) __half g_w2b[DM*2*DI];

__device__ __forceinline__ float siluf(float x) { return x / (1.f + expf(-x)); }
__device__ __forceinline__ float geluf(float x) { return 0.5f * x * (1.f + erff(x * 0.7071067811865476f)); }

template<int N> __device__ __forceinline__ void cp_wait() {
    asm volatile("cp.async.wait_group %0;\n" :: "n"(N));
}
__device__ __forceinline__ void cp_commit() {
    asm volatile("cp.async.commit_group;\n");
}

// ---------------- layer-0 in_proj LUT ----------------
__global__ void k_lut(const float* __restrict__ emb, const float* __restrict__ W) {
    __shared__ float se[8*DM];
    for (int i = threadIdx.x; i < 8*DM; i += blockDim.x) se[i] = emb[i];
    __syncthreads();
    int e = blockIdx.x*blockDim.x + threadIdx.x;
    if (e >= DIP) return;
    float acc[8] = {0.f,0.f,0.f,0.f,0.f,0.f,0.f,0.f};
    const float* wr = W + (size_t)e*DM;
    for (int d = 0; d < DM; d++) {
        float wv = wr[d];
        #pragma unroll
        for (int v = 0; v < 8; v++) acc[v] += wv * se[v*DM + d];
    }
    #pragma unroll
    for (int v = 0; v < 8; v++) g_lut[(size_t)v*DIP + e] = acc[v];
}

// ---------------- time-tiled conv4 + silu: thread = 1 channel x 64 tokens ----------------
// grid (CDIM/128, NTOK/64); 128 threads. Each row read exactly once, coalesced over channels.
template<bool LUT0>
__global__ void __launch_bounds__(128) k_convT(
        const float* __restrict__ cw, const float* __restrict__ cb,
        const int* __restrict__ ids) {
    int c   = blockIdx.x*128 + threadIdx.x;   // channel 0..639
    int bt0 = blockIdx.y*64;                  // first token of strip (within one sequence)
    int t0  = bt0 & (SEQ-1);

    float k0 = cw[c*4+0], k1 = cw[c*4+1], k2 = cw[c*4+2], k3 = cw[c*4+3];
    float bias = cb[c];

    auto src = [&](int bt) -> float {
        return LUT0 ? g_lut[(size_t)__ldg(&ids[bt])*DIP + DI + c]
                    : g_zx[(size_t)bt*DIP + DI + c];
    };

    float w0 = 0.f, w1 = 0.f, w2 = 0.f;
    if (t0 >= 3) {            // strips start at multiples of 64, so t0>=3 <=> t0>0
        w0 = src(bt0-3); w1 = src(bt0-2); w2 = src(bt0-1);
    }
    #pragma unroll 4
    for (int u = 0; u < 64; u++) {
        int bt = bt0 + u;
        float cur = src(bt);
        float acc = bias + w0*k0 + w1*k1 + w2*k2 + cur*k3;
        g_xbc[(size_t)bt*CDIM + c] = siluf(acc);
        w0 = w1; w1 = w2; w2 = cur;
    }
}

// ---------------- softplus(dt) + dA (one thread per (bt,h)) ----------------
template<bool LUT0>
__global__ void k_dt(const float* __restrict__ dtb, const float* __restrict__ Alog,
                     const int* __restrict__ ids) {
    int idx = blockIdx.x*blockDim.x + threadIdx.x;
    if (idx >= NTOK*NH) return;
    int bt = idx >> 3, h = idx & 7;
    float xr = (LUT0 ? g_lut[(size_t)ids[bt]*DIP + DI + CDIM + h]
                     : g_zx[(size_t)bt*DIP + DI + CDIM + h]) + dtb[h];
    float dtv = (xr > 20.f) ? xr : log1pf(expf(xr));
    g_dt[idx] = dtv;
    g_dA[idx] = expf(dtv * (-expf(Alog[h])));
}

// ---------------- phase 1: local chunk scan ----------------
__global__ void __launch_bounds__(256) k_scan1(const float* __restrict__ Dp) {
    int h = blockIdx.x, b = blockIdx.y, c = blockIdx.z;
    int tid = threadIdx.x;
    int p = tid >> 2, q = tid & 3;
    float Dh = Dp[h];
    float hreg[16];
    #pragma unroll
    for (int i = 0; i < 16; i++) hreg[i] = 0.f;
    float pi = 1.f;

    __shared__ float sx[16][64], sB[16][64], sC[16][64];
    __shared__ float sdt[16], sdA[16];

    int tbase = c*CHUNK;
    for (int tile = 0; tile < CHUNK/16; tile++) {
        int t0 = tbase + tile*16;
        for (int i = tid; i < 16*64; i += 256) {
            int s = i >> 6, j = i & 63;
            const float* row = g_xbc + (size_t)(b*SEQ + t0 + s)*CDIM;
            sx[s][j] = row[h*HD + j];
            sB[s][j] = row[DI + j];
            sC[s][j] = row[DI + NS + j];
        }
        if (tid < 16) {
            sdt[tid] = g_dt[(b*SEQ + t0 + tid)*NH + h];
            sdA[tid] = g_dA[(b*SEQ + t0 + tid)*NH + h];
        }
        __syncthreads();
        #pragma unroll 4
        for (int s = 0; s < 16; s++) {
            float da  = sdA[s];
            pi *= da;
            float xv  = sx[s][p];
            float dtx = sdt[s] * xv;
            float y = 0.f;
            #pragma unroll
            for (int i = 0; i < 16; i++) {
                int n = q + 4*i;
                hreg[i] = hreg[i]*da + dtx*sB[s][n];
                y += hreg[i]*sC[s][n];
            }
            y += __shfl_xor_sync(0xffffffffu, y, 1);
            y += __shfl_xor_sync(0xffffffffu, y, 2);
            if (q == 0)
                g_ys[(size_t)(b*SEQ + t0 + s)*DI + h*HD + p] = y + xv*Dh;
            if (tid == 0)
                g_pi[(b*SEQ + t0 + s)*NH + h] = pi;
        }
        __syncthreads();
    }
    size_t sb = ((size_t)(b*NH + h)*NCH + c)*(HD*NS);
    #pragma unroll
    for (int i = 0; i < 16; i++)
        g_S[sb + p*NS + q + 4*i] = hreg[i];
}

// ---------------- phase 2: chunk-state prefix (software-pipelined loads) ----------------
__global__ void __launch_bounds__(256) k_scan2() {
    int h = blockIdx.x, b = blockIdx.y;
    int tid = threadIdx.x;
    size_t base = (size_t)(b*NH + h)*NCH*(HD*NS);

    float Ac[NCH];
    #pragma unroll
    for (int c = 0; c < NCH; c++)
        Ac[c] = g_pi[(b*SEQ + c*CHUNK + CHUNK-1)*NH + h];

    float H[16], Sc[16];
    #pragma unroll
    for (int j = 0; j < 16; j++) H[j] = 0.f;
    #pragma unroll
    for (int j = 0; j < 16; j++) Sc[j] = g_S[base + tid*16 + j];

    #pragma unroll
    for (int c = 0; c < NCH; c++) {
        float Sn[16];
        if (c + 1 < NCH) {
            size_t noff = base + (size_t)(c+1)*(HD*NS) + tid*16;
            #pragma unroll
            for (int j = 0; j < 16; j++) Sn[j] = g_S[noff + j];
        }
        size_t off = base + (size_t)c*(HD*NS) + tid*16;
        #pragma unroll
        for (int j = 0; j < 16; j++) {
            float hp = H[j];
            g_S[off + j] = hp;
            H[j] = Ac[c]*hp + Sc[j];
        }
        #pragma unroll
        for (int j = 0; j < 16; j++) Sc[j] = Sn[j];
    }
}

// ---------------- phase 3: cross-chunk correction ----------------
__global__ void __launch_bounds__(256) k_scan3() {
    int h = blockIdx.x, b = blockIdx.y, c = blockIdx.z + 1;
    int tid = threadIdx.x;
    int pp = tid & 63, g = tid >> 6;

    __shared__ float sH[64][65];
    __shared__ float sC[16][64];
    __shared__ float spi[16];

    size_t hb = ((size_t)(b*NH + h)*NCH + c)*(HD*NS);
    for (int e = tid; e < HD*NS; e += 256)
        sH[e >> 6][e & 63] = g_S[hb + e];

    for (int tile = 0; tile < CHUNK/16; tile++) {
        int t0 = c*CHUNK + tile*16;
        __syncthreads();
        for (int i = tid; i < 16*64; i += 256) {
            int s = i >> 6, n = i & 63;
            sC[s][n] = g_xbc[(size_t)(b*SEQ + t0 + s)*CDIM + DI + NS + n];
        }
        if (tid < 16)
            spi[tid] = g_pi[(b*SEQ + t0 + tid)*NH + h];
        __syncthreads();
        #pragma unroll
        for (int u = 0; u < 4; u++) {
            int s = g*4 + u;
            float y = 0.f;
            #pragma unroll 16
            for (int n = 0; n < 64; n++)
                y += sC[s][n]*sH[pp][n];
            g_ys[(size_t)(b*SEQ + t0 + s)*DI + h*HD + pp] += spi[s]*y;
        }
    }
}

// ---------------- gate + RMSNorm -> fp16 pair g_a2 = [Ah | Al] ----------------
template<bool LUT0>
__global__ void k_gate(const float* __restrict__ nw, const int* __restrict__ ids) {
    int bt = blockIdx.x, tid = threadIdx.x;
    const float* ysr = g_ys + (size_t)bt*DI;
    const float* zr  = LUT0 ? (g_lut + (size_t)ids[bt]*DIP) : (g_zx + (size_t)bt*DIP);
    float v0 = ysr[tid]       * siluf(zr[tid]);
    float v1 = ysr[tid + 256] * siluf(zr[tid + 256]);
    __shared__ float red[256];
    red[tid] = v0*v0 + v1*v1;
    __syncthreads();
    for (int s = 128; s > 0; s >>= 1) {
        if (tid < s) red[tid] += red[tid + s];
        __syncthreads();
    }
    float scale = rsqrtf(red[0] * (1.f/DI) + 1e-5f);
    __half* a2 = g_a2 + (size_t)bt*(2*DI);
    float y0 = v0*scale*nw[tid];
    float y1 = v1*scale*nw[tid + 256];
    __half h0 = __float2half_rn(y0);
    __half l0 = __float2half_rn(y0 - __half2float(h0));
    __half h1 = __float2half_rn(y1);
    __half l1 = __float2half_rn(y1 - __half2float(h1));
    a2[tid] = h0;       a2[DI + tid] = l0;
    a2[tid + 256] = h1; a2[DI + tid + 256] = l1;
}

// ---------------- weight pair conversion: W2 = [Wf | Wf] ----------------
__global__ void k_cvtW(const float* __restrict__ W, __half* __restrict__ W2,
                       int N, int Npad, int K) {
    int idx = blockIdx.x*blockDim.x + threadIdx.x;
    if (idx >= Npad*K) return;
    int n = idx / K, k = idx % K;
    float w = (n < N) ? W[(size_t)n*K + k] : 0.f;
    __half hf = __float2half_rn(w);
    __half* row = W2 + (size_t)n*(2*K);
    row[k] = hf; row[K + k] = hf;
}

// ---------------- 3-stage pipelined tensor-core GEMM (mma.sync fp16, fp32 acc) ----------------
#define GBM 128
#define GBN 128
#define GBK 32
#define STG 3
#define LDA (GBK+8)
#define SMEM_MMA (STG*2*GBM*LDA*2)

template<int RESID_MODE, bool X2OUT>
__global__ void __launch_bounds__(256) k_mma(
        const __half* __restrict__ A,
        const __half* __restrict__ W,
        const float* __restrict__ R,
        const int* __restrict__ ids,
        const float* __restrict__ emb,
        float* __restrict__ C,
        __half* __restrict__ X2,
        int N, int Kp, int ldc)
{
    extern __shared__ __half smp[];
    __half* Asm = smp;
    __half* Wsm = smp + STG*GBM*LDA;

    int tid = threadIdx.x;
    int warp = tid >> 5, lane = tid & 31;
    int wm = warp >> 2, wn = warp & 3;
    int m0 = blockIdx.y * GBM;
    int n0 = blockIdx.x * GBN;

    float acc[4][4][4];
    #pragma unroll
    for (int i = 0; i < 4; i++)
        #pragma unroll
        for (int j = 0; j < 4; j++)
            #pragma unroll
            for (int e = 0; e < 4; e++) acc[i][j][e] = 0.f;

    int nk = Kp / GBK;

    auto load_stage = [&](int st, int k0) {
        __half* as = Asm + st*GBM*LDA;
        __half* ws = Wsm + st*GBM*LDA;
        #pragma unroll
        for (int u = 0; u < 2; u++) {
            int idx = tid + u*256;
            int r = idx >> 2, kc = (idx & 3)*8;
            unsigned da = (unsigned)__cvta_generic_to_shared(as + r*LDA + kc);
            asm volatile("cp.async.cg.shared.global [%0], [%1], 16;\n"
                :: "r"(da), "l"(A + (size_t)(m0 + r)*Kp + k0 + kc));
            unsigned dw = (unsigned)__cvta_generic_to_shared(ws + r*LDA + kc);
            asm volatile("cp.async.cg.shared.global [%0], [%1], 16;\n"
                :: "r"(dw), "l"(W + (size_t)(n0 + r)*Kp + k0 + kc));
        }
    };

    load_stage(0, 0);
    cp_commit();
    load_stage(1, GBK);
    cp_commit();

    for (int it = 0; it < nk; it++) {
        cp_wait<1>();
        __syncthreads();
        if (it + 2 < nk) {
            load_stage((it + 2) % STG, (it + 2)*GBK);
            cp_commit();
        } else {
            cp_commit();
        }
        int st = it % STG;
        __half* as = Asm + st*GBM*LDA;
        __half* ws = Wsm + st*GBM*LDA;

        #pragma unroll
        for (int kk = 0; kk < GBK; kk += 16) {
            unsigned af[4][4];
            #pragma unroll
            for (int i = 0; i < 4; i++) {
                int row = wm*64 + i*16 + (lane & 15);
                int col = kk + ((lane >> 4) << 3);
                unsigned addr = (unsigned)__cvta_generic_to_shared(as + row*LDA + col);
                asm volatile("ldmatrix.sync.aligned.m8n8.x4.shared.b16 {%0,%1,%2,%3}, [%4];\n"
                    : "=r"(af[i][0]), "=r"(af[i][1]), "=r"(af[i][2]), "=r"(af[i][3]) : "r"(addr));
            }
            unsigned bfm[2][4];
            #pragma unroll
            for (int g = 0; g < 2; g++) {
                int row = wn*32 + g*16 + (lane & 15);
                int col = kk + ((lane >> 4) << 3);
                unsigned addr = (unsigned)__cvta_generic_to_shared(ws + row*LDA + col);
                asm volatile("ldmatrix.sync.aligned.m8n8.x4.shared.b16 {%0,%1,%2,%3}, [%4];\n"
                    : "=r"(bfm[g][0]), "=r"(bfm[g][1]), "=r"(bfm[g][2]), "=r"(bfm[g][3]) : "r"(addr));
            }
            #pragma unroll
            for (int i = 0; i < 4; i++) {
                #pragma unroll
                for (int g = 0; g < 2; g++) {
                    #pragma unroll
                    for (int s = 0; s < 2; s++) {
                        int j = g*2 + s;
                        asm volatile(
                            "mma.sync.aligned.m16n8k16.row.col.f32.f16.f16.f32 "
                            "{%0,%1,%2,%3}, {%4,%5,%6,%7}, {%8,%9}, {%0,%1,%2,%3};\n"
                            : "+f"(acc[i][j][0]), "+f"(acc[i][j][1]),
                              "+f"(acc[i][j][2]), "+f"(acc[i][j][3])
                            : "r"(af[i][0]), "r"(af[i][1]), "r"(af[i][2]), "r"(af[i][3]),
                              "r"(bfm[g][s]), "r"(bfm[g][s+2]));
                    }
                }
            }
        }
    }

    // epilogue
    #pragma unroll
    for (int i = 0; i < 4; i++) {
        #pragma unroll
        for (int half_ = 0; half_ < 2; half_++) {
            int m = m0 + wm*64 + i*16 + (lane >> 2) + half_*8;
            const float* rrow = nullptr;
            if (RESID_MODE == 1) rrow = R + (size_t)m*ldc;
            if (RESID_MODE == 2) rrow = emb + (size_t)ids[m]*DM;
            #pragma unroll
            for (int j = 0; j < 4; j++) {
                int ncol = n0 + wn*32 + j*8 + (lane & 3)*2;
                #pragma unroll
                for (int e = 0; e < 2; e++) {
                    int n = ncol + e;
                    if (n < N) {
                        float v = acc[i][j][half_*2 + e];
                        if (RESID_MODE) v += rrow[n];
                        C[(size_t)m*ldc + n] = v;
                        if (X2OUT) {
                            __half hh = __float2half_rn(v);
                            __half ll = __float2half_rn(v - __half2float(hh));
                            __half* row = X2 + (size_t)m*(2*N);
                            row[n] = hh; row[N + n] = ll;
                        }
                    }
                }
            }
        }
    }
}

// ---------------- pooling ----------------
__global__ void k_pool1() {
    int seg = blockIdx.x, b = blockIdx.y, d = threadIdx.x;
    float sum = 0.f, mx = -INFINITY;
    for (int i = 0; i < 64; i++) {
        float v = g_x[(size_t)(b*SEQ + seg*64 + i)*DM + d];
        sum += v; mx = fmaxf(mx, v);
    }
    g_psum[(b*16 + seg)*DM + d] = sum;
    g_pmax[(b*16 + seg)*DM + d] = mx;
}
__global__ void k_pool2() {
    int b = blockIdx.x, d = threadIdx.x;
    float sum = 0.f, mx = -INFINITY;
    for (int s = 0; s < 16; s++) {
        sum += g_psum[(b*16 + s)*DM + d];
        mx = fmaxf(mx, g_pmax[(b*16 + s)*DM + d]);
    }
    g_pooled[b*DM + d] = (sum*(1.f/SEQ) + mx)*0.5f;
}

// ---------------- classification head ----------------
__global__ void k_head(const float* __restrict__ pw, const float* __restrict__ pb,
                       const float* __restrict__ c1w, const float* __restrict__ c1b,
                       const float* __restrict__ c2w, const float* __restrict__ c2b,
                       float* __restrict__ out) {
    int b = blockIdx.x, tid = threadIdx.x;
    __shared__ float sp[DM], s1[DM], s2[128];
    sp[tid] = g_pooled[b*DM + tid];
    __syncthreads();
    {
        float acc = pb[tid];
        const float* wr = pw + (size_t)tid*DM;
        for (int d = 0; d < DM; d++) acc += sp[d]*wr[d];
        s1[tid] = geluf(acc);
    }
    __syncthreads();
    if (tid < 128) {
        float acc = c1b[tid];
        const float* wr = c1w + (size_t)tid*DM;
        for (int d = 0; d < DM; d++) acc += s1[d]*wr[d];
        s2[tid] = geluf(acc);
    }
    __syncthreads();
    if (tid < 2) {
        float acc = c2b[tid];
        const float* wr = c2w + tid*128;
        for (int d = 0; d < 128; d++) acc += s2[d]*wr[d];
        out[b*2 + tid] = acc;
    }
}

// ---------------- launch ----------------
extern "C" void kernel_launch(void* const* d_in, const int* in_sizes, int n_in,
                              void* d_out, int out_size) {
    const int*   ids  = (const int*)  d_in[0];
    const float* emb  = (const float*)d_in[1];
    const float* inw  = (const float*)d_in[2];
    const float* cw   = (const float*)d_in[3];
    const float* cb   = (const float*)d_in[4];
    const float* dtb  = (const float*)d_in[5];
    const float* alog = (const float*)d_in[6];
    const float* Dv   = (const float*)d_in[7];
    const float* nw   = (const float*)d_in[8];
    const float* ow   = (const float*)d_in[9];
    const float* pw   = (const float*)d_in[10];
    const float* pb   = (const float*)d_in[11];
    const float* c1w  = (const float*)d_in[12];
    const float* c1b  = (const float*)d_in[13];
    const float* c2w  = (const float*)d_in[14];
    const float* c2b  = (const float*)d_in[15];
    float* out = (float*)d_out;

    float *px, *pzx;
    __half *pa2, *px2, *pw2a, *pw2b;
    cudaGetSymbolAddress((void**)&px,   g_x);
    cudaGetSymbolAddress((void**)&pzx,  g_zx);
    cudaGetSymbolAddress((void**)&pa2,  g_a2);
    cudaGetSymbolAddress((void**)&px2,  g_x2);
    cudaGetSymbolAddress((void**)&pw2a, g_w2a);
    cudaGetSymbolAddress((void**)&pw2b, g_w2b);

    cudaFuncSetAttribute(k_mma<2, true>,
        cudaFuncAttributeMaxDynamicSharedMemorySize, SMEM_MMA);
    cudaFuncSetAttribute(k_mma<0, false>,
        cudaFuncAttributeMaxDynamicSharedMemorySize, SMEM_MMA);
    cudaFuncSetAttribute(k_mma<1, false>,
        cudaFuncAttributeMaxDynamicSharedMemorySize, SMEM_MMA);

    // ---- layer 0 (launch #4 = k_convT for profiling) ----
    k_cvtW<<<(NPAD_IN*DM + 255)/256, 256>>>(inw + (size_t)DIP*DM, pw2a, DIP, NPAD_IN, DM);
    k_lut<<<(DIP + 255)/256, 256>>>(emb, inw);
    k_cvtW<<<(DM*DI + 255)/256, 256>>>(ow, pw2b, DM, DM, DI);
    k_convT<true><<<dim3(CDIM/128, NTOK/64), 128>>>(cw, cb, ids);
    k_dt<true><<<(NTOK*NH + 255)/256, 256>>>(dtb, alog, ids);
    k_scan1<<<dim3(NH, BATCH, NCH), 256>>>(Dv);
    k_scan2<<<dim3(NH, BATCH), 256>>>();
    k_scan3<<<dim3(NH, BATCH, NCH-1), 256>>>();
    k_gate<true><<<NTOK, 256>>>(nw, ids);
    k_mma<2, true><<<dim3(DM/GBN, NTOK/GBM), 256, SMEM_MMA>>>(
        pa2, pw2b, nullptr, ids, emb, px, px2, DM, 2*DI, DM);

    // ---- layer 1 ----
    k_mma<0, false><<<dim3(NPAD_IN/GBN, NTOK/GBM), 256, SMEM_MMA>>>(
        px2, pw2a, nullptr, nullptr, nullptr, pzx, nullptr, DIP, 2*DM, DIP);
    k_convT<false><<<dim3(CDIM/128, NTOK/64), 128>>>(cw + (size_t)CDIM*4, cb + CDIM, ids);
    k_dt<false><<<(NTOK*NH + 255)/256, 256>>>(dtb + NH, alog + NH, ids);
    k_scan1<<<dim3(NH, BATCH, NCH), 256>>>(Dv + NH);
    k_scan2<<<dim3(NH, BATCH), 256>>>();
    k_scan3<<<dim3(NH, BATCH, NCH-1), 256>>>();
    k_gate<false><<<NTOK, 256>>>(nw + DI, ids);
    k_cvtW<<<(DM*DI + 255)/256, 256>>>(ow + (size_t)DM*DI, pw2b, DM, DM, DI);
    k_mma<1, false><<<dim3(DM/GBN, NTOK/GBM), 256, SMEM_MMA>>>(
        pa2, pw2b, px, nullptr, nullptr, px, nullptr, DM, 2*DI, DM);

    k_pool1<<<dim3(16, BATCH), DM>>>();
    k_pool2<<<BATCH, DM>>>();
    k_head<<<BATCH, DM>>>(pw, pb, c1w, c1b, c2w, c2b, out);
}

// round 17
// speedup vs baseline: 1.3235x; 1.0856x over previous
#include <cuda_runtime.h>
#include <cuda_fp16.h>
#include <cstdint>
#include <math.h>

#define BATCH 8
#define SEQ   1024
#define DM    256
#define DI    512
#define NH    8
#define HD    64
#define NS    64
#define CDIM  640
#define DIP   1160
#define NTOK  (BATCH*SEQ)   // 8192
#define NPAD_IN 1280        // 10*128
#define NCH   16
#define CHUNK 64            // SEQ / NCH

// ---------------- device scratch ----------------
__device__ __align__(16) float g_x[NTOK*DM];
__device__ __align__(16) float g_zx[NTOK*DIP];
__device__ __align__(16) float g_xbc[NTOK*CDIM];
__device__ float g_dt[NTOK*NH];
__device__ float g_dA[NTOK*NH];
__device__ float g_pi[NTOK*NH];
__device__ __align__(16) float g_S[(size_t)BATCH*NH*NCH*HD*NS];
__device__ __align__(16) float g_ys[NTOK*DI];
__device__ __align__(16) float g_lut[8*DIP];
__device__ float g_psum[BATCH*16*DM];
__device__ float g_pmax[BATCH*16*DM];
__device__ float g_pooled[BATCH*DM];
// single-fp16 GEMM operands (fp32 accumulate)
__device__ __align__(16) __half g_a1[NTOK*DI];
__device__ __align__(16) __half g_x1[NTOK*DM];
__device__ __align__(16) __half g_w1a[NPAD_IN*DM];
__device__ __align__(16) __half g_w1b[DM*DI];

__device__ __forceinline__ float siluf(float x) { return x / (1.f + expf(-x)); }
__device__ __forceinline__ float geluf(float x) { return 0.5f * x * (1.f + erff(x * 0.7071067811865476f)); }

template<int N> __device__ __forceinline__ void cp_wait() {
    asm volatile("cp.async.wait_group %0;\n" :: "n"(N));
}
__device__ __forceinline__ void cp_commit() {
    asm volatile("cp.async.commit_group;\n");
}

// ---------------- layer-0 in_proj LUT ----------------
__global__ void k_lut(const float* __restrict__ emb, const float* __restrict__ W) {
    __shared__ float se[8*DM];
    for (int i = threadIdx.x; i < 8*DM; i += blockDim.x) se[i] = emb[i];
    __syncthreads();
    int e = blockIdx.x*blockDim.x + threadIdx.x;
    if (e >= DIP) return;
    float acc[8] = {0.f,0.f,0.f,0.f,0.f,0.f,0.f,0.f};
    const float* wr = W + (size_t)e*DM;
    for (int d = 0; d < DM; d++) {
        float wv = wr[d];
        #pragma unroll
        for (int v = 0; v < 8; v++) acc[v] += wv * se[v*DM + d];
    }
    #pragma unroll
    for (int v = 0; v < 8; v++) g_lut[(size_t)v*DIP + e] = acc[v];
}

// ---------------- time-tiled conv4 + silu ----------------
template<bool LUT0>
__global__ void __launch_bounds__(128) k_convT(
        const float* __restrict__ cw, const float* __restrict__ cb,
        const int* __restrict__ ids) {
    int c   = blockIdx.x*128 + threadIdx.x;
    int bt0 = blockIdx.y*64;
    int t0  = bt0 & (SEQ-1);

    float k0 = cw[c*4+0], k1 = cw[c*4+1], k2 = cw[c*4+2], k3 = cw[c*4+3];
    float bias = cb[c];

    auto src = [&](int bt) -> float {
        return LUT0 ? g_lut[(size_t)__ldg(&ids[bt])*DIP + DI + c]
                    : g_zx[(size_t)bt*DIP + DI + c];
    };

    float w0 = 0.f, w1 = 0.f, w2 = 0.f;
    if (t0 >= 3) {
        w0 = src(bt0-3); w1 = src(bt0-2); w2 = src(bt0-1);
    }
    #pragma unroll 4
    for (int u = 0; u < 64; u++) {
        int bt = bt0 + u;
        float cur = src(bt);
        float acc = bias + w0*k0 + w1*k1 + w2*k2 + cur*k3;
        g_xbc[(size_t)bt*CDIM + c] = siluf(acc);
        w0 = w1; w1 = w2; w2 = cur;
    }
}

// ---------------- softplus(dt) + dA ----------------
template<bool LUT0>
__global__ void k_dt(const float* __restrict__ dtb, const float* __restrict__ Alog,
                     const int* __restrict__ ids) {
    int idx = blockIdx.x*blockDim.x + threadIdx.x;
    if (idx >= NTOK*NH) return;
    int bt = idx >> 3, h = idx & 7;
    float xr = (LUT0 ? g_lut[(size_t)ids[bt]*DIP + DI + CDIM + h]
                     : g_zx[(size_t)bt*DIP + DI + CDIM + h]) + dtb[h];
    float dtv = (xr > 20.f) ? xr : log1pf(expf(xr));
    g_dt[idx] = dtv;
    g_dA[idx] = expf(dtv * (-expf(Alog[h])));
}

// ---------------- phase 1: local chunk scan ----------------
__global__ void __launch_bounds__(256) k_scan1(const float* __restrict__ Dp) {
    int h = blockIdx.x, b = blockIdx.y, c = blockIdx.z;
    int tid = threadIdx.x;
    int p = tid >> 2, q = tid & 3;
    float Dh = Dp[h];
    float hreg[16];
    #pragma unroll
    for (int i = 0; i < 16; i++) hreg[i] = 0.f;
    float pi = 1.f;

    __shared__ float sx[16][64], sB[16][64], sC[16][64];
    __shared__ float sdt[16], sdA[16];

    int tbase = c*CHUNK;
    for (int tile = 0; tile < CHUNK/16; tile++) {
        int t0 = tbase + tile*16;
        for (int i = tid; i < 16*64; i += 256) {
            int s = i >> 6, j = i & 63;
            const float* row = g_xbc + (size_t)(b*SEQ + t0 + s)*CDIM;
            sx[s][j] = row[h*HD + j];
            sB[s][j] = row[DI + j];
            sC[s][j] = row[DI + NS + j];
        }
        if (tid < 16) {
            sdt[tid] = g_dt[(b*SEQ + t0 + tid)*NH + h];
            sdA[tid] = g_dA[(b*SEQ + t0 + tid)*NH + h];
        }
        __syncthreads();
        #pragma unroll 4
        for (int s = 0; s < 16; s++) {
            float da  = sdA[s];
            pi *= da;
            float xv  = sx[s][p];
            float dtx = sdt[s] * xv;
            float y = 0.f;
            #pragma unroll
            for (int i = 0; i < 16; i++) {
                int n = q + 4*i;
                hreg[i] = hreg[i]*da + dtx*sB[s][n];
                y += hreg[i]*sC[s][n];
            }
            y += __shfl_xor_sync(0xffffffffu, y, 1);
            y += __shfl_xor_sync(0xffffffffu, y, 2);
            if (q == 0)
                g_ys[(size_t)(b*SEQ + t0 + s)*DI + h*HD + p] = y + xv*Dh;
            if (tid == 0)
                g_pi[(b*SEQ + t0 + s)*NH + h] = pi;
        }
        __syncthreads();
    }
    size_t sb = ((size_t)(b*NH + h)*NCH + c)*(HD*NS);
    #pragma unroll
    for (int i = 0; i < 16; i++)
        g_S[sb + p*NS + q + 4*i] = hreg[i];
}

// ---------------- phase 2: chunk-state prefix ----------------
__global__ void __launch_bounds__(256) k_scan2() {
    int h = blockIdx.x, b = blockIdx.y;
    int tid = threadIdx.x;
    size_t base = (size_t)(b*NH + h)*NCH*(HD*NS);

    float Ac[NCH];
    #pragma unroll
    for (int c = 0; c < NCH; c++)
        Ac[c] = g_pi[(b*SEQ + c*CHUNK + CHUNK-1)*NH + h];

    float H[16], Sc[16];
    #pragma unroll
    for (int j = 0; j < 16; j++) H[j] = 0.f;
    #pragma unroll
    for (int j = 0; j < 16; j++) Sc[j] = g_S[base + tid*16 + j];

    #pragma unroll
    for (int c = 0; c < NCH; c++) {
        float Sn[16];
        if (c + 1 < NCH) {
            size_t noff = base + (size_t)(c+1)*(HD*NS) + tid*16;
            #pragma unroll
            for (int j = 0; j < 16; j++) Sn[j] = g_S[noff + j];
        }
        size_t off = base + (size_t)c*(HD*NS) + tid*16;
        #pragma unroll
        for (int j = 0; j < 16; j++) {
            float hp = H[j];
            g_S[off + j] = hp;
            H[j] = Ac[c]*hp + Sc[j];
        }
        #pragma unroll
        for (int j = 0; j < 16; j++) Sc[j] = Sn[j];
    }
}

// ---------------- phase 3: cross-chunk correction ----------------
__global__ void __launch_bounds__(256) k_scan3() {
    int h = blockIdx.x, b = blockIdx.y, c = blockIdx.z + 1;
    int tid = threadIdx.x;
    int pp = tid & 63, g = tid >> 6;

    __shared__ float sH[64][65];
    __shared__ float sC[16][64];
    __shared__ float spi[16];

    size_t hb = ((size_t)(b*NH + h)*NCH + c)*(HD*NS);
    for (int e = tid; e < HD*NS; e += 256)
        sH[e >> 6][e & 63] = g_S[hb + e];

    for (int tile = 0; tile < CHUNK/16; tile++) {
        int t0 = c*CHUNK + tile*16;
        __syncthreads();
        for (int i = tid; i < 16*64; i += 256) {
            int s = i >> 6, n = i & 63;
            sC[s][n] = g_xbc[(size_t)(b*SEQ + t0 + s)*CDIM + DI + NS + n];
        }
        if (tid < 16)
            spi[tid] = g_pi[(b*SEQ + t0 + tid)*NH + h];
        __syncthreads();
        #pragma unroll
        for (int u = 0; u < 4; u++) {
            int s = g*4 + u;
            float y = 0.f;
            #pragma unroll 16
            for (int n = 0; n < 64; n++)
                y += sC[s][n]*sH[pp][n];
            g_ys[(size_t)(b*SEQ + t0 + s)*DI + h*HD + pp] += spi[s]*y;
        }
    }
}

// ---------------- gate + RMSNorm -> single fp16 g_a1 ----------------
template<bool LUT0>
__global__ void k_gate(const float* __restrict__ nw, const int* __restrict__ ids) {
    int bt = blockIdx.x, tid = threadIdx.x;
    const float* ysr = g_ys + (size_t)bt*DI;
    const float* zr  = LUT0 ? (g_lut + (size_t)ids[bt]*DIP) : (g_zx + (size_t)bt*DIP);
    float v0 = ysr[tid]       * siluf(zr[tid]);
    float v1 = ysr[tid + 256] * siluf(zr[tid + 256]);
    __shared__ float red[256];
    red[tid] = v0*v0 + v1*v1;
    __syncthreads();
    for (int s = 128; s > 0; s >>= 1) {
        if (tid < s) red[tid] += red[tid + s];
        __syncthreads();
    }
    float scale = rsqrtf(red[0] * (1.f/DI) + 1e-5f);
    __half* a1 = g_a1 + (size_t)bt*DI;
    a1[tid]       = __float2half_rn(v0*scale*nw[tid]);
    a1[tid + 256] = __float2half_rn(v1*scale*nw[tid + 256]);
}

// ---------------- weight conversion: single fp16 ----------------
__global__ void k_cvtW(const float* __restrict__ W, __half* __restrict__ W1,
                       int N, int Npad, int K) {
    int idx = blockIdx.x*blockDim.x + threadIdx.x;
    if (idx >= Npad*K) return;
    int n = idx / K, k = idx % K;
    float w = (n < N) ? W[(size_t)n*K + k] : 0.f;
    W1[(size_t)n*K + k] = __float2half_rn(w);
}

// ---------------- 3-stage pipelined tensor-core GEMM (mma.sync fp16, fp32 acc) ----------------
#define GBM 128
#define GBN 128
#define GBK 32
#define STG 3
#define LDA (GBK+8)
#define SMEM_MMA (STG*2*GBM*LDA*2)

template<int RESID_MODE, bool X1OUT>
__global__ void __launch_bounds__(256) k_mma(
        const __half* __restrict__ A,
        const __half* __restrict__ W,
        const float* __restrict__ R,
        const int* __restrict__ ids,
        const float* __restrict__ emb,
        float* __restrict__ C,
        __half* __restrict__ X1,
        int N, int Kp, int ldc)
{
    extern __shared__ __half smp[];
    __half* Asm = smp;
    __half* Wsm = smp + STG*GBM*LDA;

    int tid = threadIdx.x;
    int warp = tid >> 5, lane = tid & 31;
    int wm = warp >> 2, wn = warp & 3;
    int m0 = blockIdx.y * GBM;
    int n0 = blockIdx.x * GBN;

    float acc[4][4][4];
    #pragma unroll
    for (int i = 0; i < 4; i++)
        #pragma unroll
        for (int j = 0; j < 4; j++)
            #pragma unroll
            for (int e = 0; e < 4; e++) acc[i][j][e] = 0.f;

    int nk = Kp / GBK;

    auto load_stage = [&](int st, int k0) {
        __half* as = Asm + st*GBM*LDA;
        __half* ws = Wsm + st*GBM*LDA;
        #pragma unroll
        for (int u = 0; u < 2; u++) {
            int idx = tid + u*256;
            int r = idx >> 2, kc = (idx & 3)*8;
            unsigned da = (unsigned)__cvta_generic_to_shared(as + r*LDA + kc);
            asm volatile("cp.async.cg.shared.global [%0], [%1], 16;\n"
                :: "r"(da), "l"(A + (size_t)(m0 + r)*Kp + k0 + kc));
            unsigned dw = (unsigned)__cvta_generic_to_shared(ws + r*LDA + kc);
            asm volatile("cp.async.cg.shared.global [%0], [%1], 16;\n"
                :: "r"(dw), "l"(W + (size_t)(n0 + r)*Kp + k0 + kc));
        }
    };

    load_stage(0, 0);
    cp_commit();
    load_stage(1, GBK);
    cp_commit();

    for (int it = 0; it < nk; it++) {
        cp_wait<1>();
        __syncthreads();
        if (it + 2 < nk) {
            load_stage((it + 2) % STG, (it + 2)*GBK);
            cp_commit();
        } else {
            cp_commit();
        }
        int st = it % STG;
        __half* as = Asm + st*GBM*LDA;
        __half* ws = Wsm + st*GBM*LDA;

        #pragma unroll
        for (int kk = 0; kk < GBK; kk += 16) {
            unsigned af[4][4];
            #pragma unroll
            for (int i = 0; i < 4; i++) {
                int row = wm*64 + i*16 + (lane & 15);
                int col = kk + ((lane >> 4) << 3);
                unsigned addr = (unsigned)__cvta_generic_to_shared(as + row*LDA + col);
                asm volatile("ldmatrix.sync.aligned.m8n8.x4.shared.b16 {%0,%1,%2,%3}, [%4];\n"
                    : "=r"(af[i][0]), "=r"(af[i][1]), "=r"(af[i][2]), "=r"(af[i][3]) : "r"(addr));
            }
            unsigned bfm[2][4];
            #pragma unroll
            for (int g = 0; g < 2; g++) {
                int row = wn*32 + g*16 + (lane & 15);
                int col = kk + ((lane >> 4) << 3);
                unsigned addr = (unsigned)__cvta_generic_to_shared(ws + row*LDA + col);
                asm volatile("ldmatrix.sync.aligned.m8n8.x4.shared.b16 {%0,%1,%2,%3}, [%4];\n"
                    : "=r"(bfm[g][0]), "=r"(bfm[g][1]), "=r"(bfm[g][2]), "=r"(bfm[g][3]) : "r"(addr));
            }
            #pragma unroll
            for (int i = 0; i < 4; i++) {
                #pragma unroll
                for (int g = 0; g < 2; g++) {
                    #pragma unroll
                    for (int s = 0; s < 2; s++) {
                        int j = g*2 + s;
                        asm volatile(
                            "mma.sync.aligned.m16n8k16.row.col.f32.f16.f16.f32 "
                            "{%0,%1,%2,%3}, {%4,%5,%6,%7}, {%8,%9}, {%0,%1,%2,%3};\n"
                            : "+f"(acc[i][j][0]), "+f"(acc[i][j][1]),
                              "+f"(acc[i][j][2]), "+f"(acc[i][j][3])
                            : "r"(af[i][0]), "r"(af[i][1]), "r"(af[i][2]), "r"(af[i][3]),
                              "r"(bfm[g][s]), "r"(bfm[g][s+2]));
                    }
                }
            }
        }
    }

    // epilogue
    #pragma unroll
    for (int i = 0; i < 4; i++) {
        #pragma unroll
        for (int half_ = 0; half_ < 2; half_++) {
            int m = m0 + wm*64 + i*16 + (lane >> 2) + half_*8;
            const float* rrow = nullptr;
            if (RESID_MODE == 1) rrow = R + (size_t)m*ldc;
            if (RESID_MODE == 2) rrow = emb + (size_t)ids[m]*DM;
            #pragma unroll
            for (int j = 0; j < 4; j++) {
                int ncol = n0 + wn*32 + j*8 + (lane & 3)*2;
                #pragma unroll
                for (int e = 0; e < 2; e++) {
                    int n = ncol + e;
                    if (n < N) {
                        float v = acc[i][j][half_*2 + e];
                        if (RESID_MODE) v += rrow[n];
                        C[(size_t)m*ldc + n] = v;
                        if (X1OUT)
                            X1[(size_t)m*N + n] = __float2half_rn(v);
                    }
                }
            }
        }
    }
}

// ---------------- pooling ----------------
__global__ void k_pool1() {
    int seg = blockIdx.x, b = blockIdx.y, d = threadIdx.x;
    float sum = 0.f, mx = -INFINITY;
    for (int i = 0; i < 64; i++) {
        float v = g_x[(size_t)(b*SEQ + seg*64 + i)*DM + d];
        sum += v; mx = fmaxf(mx, v);
    }
    g_psum[(b*16 + seg)*DM + d] = sum;
    g_pmax[(b*16 + seg)*DM + d] = mx;
}
__global__ void k_pool2() {
    int b = blockIdx.x, d = threadIdx.x;
    float sum = 0.f, mx = -INFINITY;
    for (int s = 0; s < 16; s++) {
        sum += g_psum[(b*16 + s)*DM + d];
        mx = fmaxf(mx, g_pmax[(b*16 + s)*DM + d]);
    }
    g_pooled[b*DM + d] = (sum*(1.f/SEQ) + mx)*0.5f;
}

// ---------------- classification head ----------------
__global__ void k_head(const float* __restrict__ pw, const float* __restrict__ pb,
                       const float* __restrict__ c1w, const float* __restrict__ c1b,
                       const float* __restrict__ c2w, const float* __restrict__ c2b,
                       float* __restrict__ out) {
    int b = blockIdx.x, tid = threadIdx.x;
    __shared__ float sp[DM], s1[DM], s2[128];
    sp[tid] = g_pooled[b*DM + tid];
    __syncthreads();
    {
        float acc = pb[tid];
        const float* wr = pw + (size_t)tid*DM;
        for (int d = 0; d < DM; d++) acc += sp[d]*wr[d];
        s1[tid] = geluf(acc);
    }
    __syncthreads();
    if (tid < 128) {
        float acc = c1b[tid];
        const float* wr = c1w + (size_t)tid*DM;
        for (int d = 0; d < DM; d++) acc += s1[d]*wr[d];
        s2[tid] = geluf(acc);
    }
    __syncthreads();
    if (tid < 2) {
        float acc = c2b[tid];
        const float* wr = c2w + tid*128;
        for (int d = 0; d < 128; d++) acc += s2[d]*wr[d];
        out[b*2 + tid] = acc;
    }
}

// ---------------- launch ----------------
extern "C" void kernel_launch(void* const* d_in, const int* in_sizes, int n_in,
                              void* d_out, int out_size) {
    const int*   ids  = (const int*)  d_in[0];
    const float* emb  = (const float*)d_in[1];
    const float* inw  = (const float*)d_in[2];
    const float* cw   = (const float*)d_in[3];
    const float* cb   = (const float*)d_in[4];
    const float* dtb  = (const float*)d_in[5];
    const float* alog = (const float*)d_in[6];
    const float* Dv   = (const float*)d_in[7];
    const float* nw   = (const float*)d_in[8];
    const float* ow   = (const float*)d_in[9];
    const float* pw   = (const float*)d_in[10];
    const float* pb   = (const float*)d_in[11];
    const float* c1w  = (const float*)d_in[12];
    const float* c1b  = (const float*)d_in[13];
    const float* c2w  = (const float*)d_in[14];
    const float* c2b  = (const float*)d_in[15];
    float* out = (float*)d_out;

    float *px, *pzx;
    __half *pa1, *px1, *pw1a, *pw1b;
    cudaGetSymbolAddress((void**)&px,   g_x);
    cudaGetSymbolAddress((void**)&pzx,  g_zx);
    cudaGetSymbolAddress((void**)&pa1,  g_a1);
    cudaGetSymbolAddress((void**)&px1,  g_x1);
    cudaGetSymbolAddress((void**)&pw1a, g_w1a);
    cudaGetSymbolAddress((void**)&pw1b, g_w1b);

    cudaFuncSetAttribute(k_mma<2, true>,
        cudaFuncAttributeMaxDynamicSharedMemorySize, SMEM_MMA);
    cudaFuncSetAttribute(k_mma<0, false>,
        cudaFuncAttributeMaxDynamicSharedMemorySize, SMEM_MMA);
    cudaFuncSetAttribute(k_mma<1, false>,
        cudaFuncAttributeMaxDynamicSharedMemorySize, SMEM_MMA);

    // ---- layer 0 ----
    k_cvtW<<<(NPAD_IN*DM + 255)/256, 256>>>(inw + (size_t)DIP*DM, pw1a, DIP, NPAD_IN, DM);
    k_lut<<<(DIP + 255)/256, 256>>>(emb, inw);
    k_cvtW<<<(DM*DI + 255)/256, 256>>>(ow, pw1b, DM, DM, DI);
    k_convT<true><<<dim3(CDIM/128, NTOK/64), 128>>>(cw, cb, ids);
    k_dt<true><<<(NTOK*NH + 255)/256, 256>>>(dtb, alog, ids);
    k_scan1<<<dim3(NH, BATCH, NCH), 256>>>(Dv);
    k_scan2<<<dim3(NH, BATCH), 256>>>();
    k_scan3<<<dim3(NH, BATCH, NCH-1), 256>>>();
    k_gate<true><<<NTOK, 256>>>(nw, ids);
    // out_proj l0: M=8192, N=256, Kp=512; residual = emb[ids]; emit fp16 x1
    k_mma<2, true><<<dim3(DM/GBN, NTOK/GBM), 256, SMEM_MMA>>>(
        pa1, pw1b, nullptr, ids, emb, px, px1, DM, DI, DM);

    // ---- layer 1 ----
    // in_proj: M=8192, N=1160 (pad 1280), Kp=256
    k_mma<0, false><<<dim3(NPAD_IN/GBN, NTOK/GBM), 256, SMEM_MMA>>>(
        px1, pw1a, nullptr, nullptr, nullptr, pzx, nullptr, DIP, DM, DIP);
    k_convT<false><<<dim3(CDIM/128, NTOK/64), 128>>>(cw + (size_t)CDIM*4, cb + CDIM, ids);
    k_dt<false><<<(NTOK*NH + 255)/256, 256>>>(dtb + NH, alog + NH, ids);
    k_scan1<<<dim3(NH, BATCH, NCH), 256>>>(Dv + NH);
    k_scan2<<<dim3(NH, BATCH), 256>>>();
    k_scan3<<<dim3(NH, BATCH, NCH-1), 256>>>();
    k_gate<false><<<NTOK, 256>>>(nw + DI, ids);
    k_cvtW<<<(DM*DI + 255)/256, 256>>>(ow + (size_t)DM*DI, pw1b, DM, DM, DI);
    k_mma<1, false><<<dim3(DM/GBN, NTOK/GBM), 256, SMEM_MMA>>>(
        pa1, pw1b, px, nullptr, nullptr, px, nullptr, DM, DI, DM);

    k_pool1<<<dim3(16, BATCH), DM>>>();
    k_pool2<<<BATCH, DM>>>();
    k_head<<<BATCH, DM>>>(pw, pb, c1w, c1b, c2w, c2b, out);
}